// round 4
// baseline (speedup 1.0000x reference)
#include <cuda_runtime.h>
#include <cuda_bf16.h>
#include <cstdint>

// ---------------------------------------------------------------------------
// RNNEncDec: Elman encoder (128 steps) + teacher-forced decoder (127 steps)
// + summed mean cross-entropy over V=32000 vocab.
//
// Shapes: H=300, B=256, NX=NY=128, V=32000, M = 127*256 = 32512.
// Strategy:
//   - fp32 recurrences, h stored transposed [k][b] (coalesced), 1 kernel/step.
//   - decoder h emitted as bf16 into A [32512][304] (K padded 300->304).
//   - outW converted once per launch to bf16 [32000][304].
//   - big GEMM (logits) via bf16 mma.sync m16n8k16, 128x128 tiles, full-K smem
//     staging, fused +outb and per-row (max, sumexp) partials per n-tile.
//   - per-row logsumexp combine + target-logit dot, deterministic reduction.
// ---------------------------------------------------------------------------

#define H     300
#define BATCH 256
#define NX    128
#define NY    128
#define V     32000
#define MROWS (127 * 256)      // 32512
#define KP    304              // padded K
#define NTILE 250              // 32000 / 128
#define MTILE 254              // 32512 / 128
#define KS    312              // smem row stride in halves (conflict-free)
#define SMEM_GEMM (2 * 128 * KS * 2)   // 159744 bytes

// ------------------------- device scratch (static, no allocs) ---------------
__device__ float g_h[2][H * BATCH];                       // transposed h, double buffered
__device__ __align__(16) __nv_bfloat16 g_A[(size_t)MROWS * KP];   // decoder h, bf16, row-major [m][k]
__device__ __align__(16) __nv_bfloat16 g_Wb[(size_t)V * KP];      // outW bf16 [n][k]
__device__ float g_pM[(size_t)MROWS * NTILE];             // per (row, ntile) max
__device__ float g_pS[(size_t)MROWS * NTILE];             // per (row, ntile) sumexp
__device__ float g_bsum[4064];                            // per-block CE partial sums

// ------------------------- init: zero h0 and A's K-pad ----------------------
__global__ void k_init() {
    int i = blockIdx.x * blockDim.x + threadIdx.x;
    if (i < H * BATCH) g_h[0][i] = 0.f;
    if (i < MROWS * 4) {
        int row = i >> 2;
        g_A[(size_t)row * KP + 300 + (i & 3)] = __float2bfloat16(0.f);
    }
}

// ------------------------- outW fp32 -> bf16 (padded) -----------------------
__global__ void k_convW(const float* __restrict__ outW) {
    int n = blockIdx.x;
    int k = threadIdx.x;
    if (k < KP) {
        float v = (k < H) ? outW[(size_t)n * H + k] : 0.f;
        g_Wb[(size_t)n * KP + k] = __float2bfloat16(v);
    }
}

// ------------------------- one recurrence step ------------------------------
// h_out[j][b] = relu( emb[idx[b]][j] + sum_k h_in[k][b] * W[j][k] + bias[j] )
// grid: (75 j-groups of 4, 2 b-halves of 128), block 256 = (128 b x 2 jq)
__global__ void __launch_bounds__(256) k_step(
    int inBuf, int outBuf,
    const int*   __restrict__ idx,
    const float* __restrict__ emb,
    const float* __restrict__ W,
    const float* __restrict__ bias,
    int tOut)   // >=0: also write bf16 h into g_A at row block tOut*256
{
    __shared__ __align__(16) float sW[4 * H];
    __shared__ float sb[4];
    int tid = threadIdx.x;
    int j0 = blockIdx.x * 4;
    for (int i = tid; i < 4 * H; i += 256) {
        int jj = i / H, k = i - jj * H;
        sW[jj * H + k] = W[(j0 + jj) * H + k];
    }
    if (tid < 4) sb[tid] = bias[j0 + tid];
    __syncthreads();

    int b  = blockIdx.y * 128 + (tid & 127);
    int jq = tid >> 7;                       // 0 or 1
    const float* __restrict__ hin = g_h[inBuf];
    const float* w0 = sW + (jq * 2) * H;
    const float* w1 = w0 + H;

    float a0 = 0.f, a1 = 0.f, a2 = 0.f, a3 = 0.f;
    #pragma unroll 5
    for (int k = 0; k < H; k += 4) {
        float h0 = hin[(k + 0) * BATCH + b];
        float h1 = hin[(k + 1) * BATCH + b];
        float h2 = hin[(k + 2) * BATCH + b];
        float h3 = hin[(k + 3) * BATCH + b];
        float4 wa = *reinterpret_cast<const float4*>(w0 + k);
        float4 wb = *reinterpret_cast<const float4*>(w1 + k);
        a0 = fmaf(h0, wa.x, a0); a2 = fmaf(h1, wa.y, a2);
        a0 = fmaf(h2, wa.z, a0); a2 = fmaf(h3, wa.w, a2);
        a1 = fmaf(h0, wb.x, a1); a3 = fmaf(h1, wb.y, a3);
        a1 = fmaf(h2, wb.z, a1); a3 = fmaf(h3, wb.w, a3);
    }
    float acc0 = a0 + a2, acc1 = a1 + a3;

    int e = idx[b];
    int j = j0 + jq * 2;
    float v0 = emb[(size_t)e * H + j]     + acc0 + sb[jq * 2];
    float v1 = emb[(size_t)e * H + j + 1] + acc1 + sb[jq * 2 + 1];
    v0 = fmaxf(v0, 0.f);
    v1 = fmaxf(v1, 0.f);

    float* hout = g_h[outBuf];
    hout[j * BATCH + b]       = v0;
    hout[(j + 1) * BATCH + b] = v1;

    if (tOut >= 0) {
        __nv_bfloat162 p = __floats2bfloat162_rn(v0, v1);
        *reinterpret_cast<__nv_bfloat162*>(
            &g_A[((size_t)tOut * BATCH + b) * KP + j]) = p;
    }
}

// ------------------------- bf16 mma helper ----------------------------------
__device__ __forceinline__ void mma16816(float* c, const uint32_t* a,
                                         uint32_t b0, uint32_t b1) {
    asm volatile(
        "mma.sync.aligned.m16n8k16.row.col.f32.bf16.bf16.f32 "
        "{%0,%1,%2,%3}, {%4,%5,%6,%7}, {%8,%9}, {%0,%1,%2,%3};\n"
        : "+f"(c[0]), "+f"(c[1]), "+f"(c[2]), "+f"(c[3])
        : "r"(a[0]), "r"(a[1]), "r"(a[2]), "r"(a[3]), "r"(b0), "r"(b1));
}

// ------------------------- big GEMM + fused partial logsumexp ---------------
// grid (NTILE, MTILE), 256 threads (8 warps: 4 M x 2 N), CTA tile 128x128.
__global__ void __launch_bounds__(256) k_gemm(const float* __restrict__ outb) {
    extern __shared__ __align__(16) unsigned char smem_raw[];
    __nv_bfloat16* As = reinterpret_cast<__nv_bfloat16*>(smem_raw);
    __nv_bfloat16* Ws = As + 128 * KS;

    int tid = threadIdx.x;
    int m0 = blockIdx.y * 128;
    int n0 = blockIdx.x * 128;

    // stage both tiles (full K=304) into smem; KP=304 halves = 38 uint4 / row
    for (int i = tid; i < 128 * 38; i += 256) {
        int r = i / 38, c = i - r * 38;
        reinterpret_cast<uint4*>(As + r * KS)[c] =
            reinterpret_cast<const uint4*>(g_A + (size_t)(m0 + r) * KP)[c];
        reinterpret_cast<uint4*>(Ws + r * KS)[c] =
            reinterpret_cast<const uint4*>(g_Wb + (size_t)(n0 + r) * KP)[c];
    }
    __syncthreads();

    int warp = tid >> 5, lane = tid & 31;
    int wm = warp & 3;          // 0..3 over M
    int wn = warp >> 2;         // 0..1 over N
    int g   = lane >> 2;        // group id 0..7
    int tig = lane & 3;         // thread in group

    float acc[2][8][4];
    #pragma unroll
    for (int a = 0; a < 2; a++)
        #pragma unroll
        for (int b = 0; b < 8; b++)
            #pragma unroll
            for (int q = 0; q < 4; q++) acc[a][b][q] = 0.f;

    const __nv_bfloat16* Abase = As + (wm * 32 + g) * KS + tig * 2;
    const __nv_bfloat16* Bbase = Ws + (wn * 64 + g) * KS + tig * 2;

    #pragma unroll 1
    for (int kc = 0; kc < 19; kc++) {
        int kb = kc * 16;
        uint32_t afr[2][4];
        #pragma unroll
        for (int mt = 0; mt < 2; mt++) {
            const __nv_bfloat16* p = Abase + mt * 16 * KS + kb;
            afr[mt][0] = *reinterpret_cast<const uint32_t*>(p);
            afr[mt][1] = *reinterpret_cast<const uint32_t*>(p + 8 * KS);
            afr[mt][2] = *reinterpret_cast<const uint32_t*>(p + 8);
            afr[mt][3] = *reinterpret_cast<const uint32_t*>(p + 8 * KS + 8);
        }
        #pragma unroll
        for (int nt = 0; nt < 8; nt++) {
            const __nv_bfloat16* p = Bbase + nt * 8 * KS + kb;
            uint32_t b0 = *reinterpret_cast<const uint32_t*>(p);
            uint32_t b1 = *reinterpret_cast<const uint32_t*>(p + 8);
            mma16816(acc[0][nt], afr[0], b0, b1);
            mma16816(acc[1][nt], afr[1], b0, b1);
        }
    }
    __syncthreads();   // done with tiles; smem reused for row reduction

    // add outb, then per-row max / sumexp over the CTA's 128 columns
    #pragma unroll
    for (int nt = 0; nt < 8; nt++) {
        float bv0 = outb[n0 + wn * 64 + nt * 8 + tig * 2];
        float bv1 = outb[n0 + wn * 64 + nt * 8 + tig * 2 + 1];
        #pragma unroll
        for (int mt = 0; mt < 2; mt++) {
            acc[mt][nt][0] += bv0; acc[mt][nt][1] += bv1;
            acc[mt][nt][2] += bv0; acc[mt][nt][3] += bv1;
        }
    }

    float rm[4], rs[4];
    #pragma unroll
    for (int r = 0; r < 4; r++) {
        int mt = r >> 1, hi = r & 1;
        float mx = -3.4e38f;
        #pragma unroll
        for (int nt = 0; nt < 8; nt++) {
            mx = fmaxf(mx, acc[mt][nt][hi * 2]);
            mx = fmaxf(mx, acc[mt][nt][hi * 2 + 1]);
        }
        mx = fmaxf(mx, __shfl_xor_sync(0xffffffffu, mx, 1));
        mx = fmaxf(mx, __shfl_xor_sync(0xffffffffu, mx, 2));
        float s = 0.f;
        #pragma unroll
        for (int nt = 0; nt < 8; nt++) {
            s += __expf(acc[mt][nt][hi * 2]     - mx);
            s += __expf(acc[mt][nt][hi * 2 + 1] - mx);
        }
        s += __shfl_xor_sync(0xffffffffu, s, 1);
        s += __shfl_xor_sync(0xffffffffu, s, 2);
        rm[r] = mx; rs[r] = s;
    }

    float* red = reinterpret_cast<float*>(smem_raw);   // 128 rows * 2 floats
    if (wn == 0 && tig == 0) {
        #pragma unroll
        for (int r = 0; r < 4; r++) {
            int rowL = wm * 32 + (r >> 1) * 16 + (r & 1) * 8 + g;
            red[rowL * 2]     = rm[r];
            red[rowL * 2 + 1] = rs[r];
        }
    }
    __syncthreads();
    if (wn == 1 && tig == 0) {
        #pragma unroll
        for (int r = 0; r < 4; r++) {
            int rowL = wm * 32 + (r >> 1) * 16 + (r & 1) * 8 + g;
            float om = red[rowL * 2], os = red[rowL * 2 + 1];
            float nm = fmaxf(rm[r], om);
            float s  = rs[r] * __expf(rm[r] - nm) + os * __expf(om - nm);
            size_t grow = (size_t)(m0 + rowL);
            g_pM[grow * NTILE + blockIdx.x] = nm;
            g_pS[grow * NTILE + blockIdx.x] = s;
        }
    }
}

// ------------------------- per-row lse + target logit -> CE -----------------
// 1 warp per row; grid 4064 blocks of 8 warps.
__global__ void __launch_bounds__(256) k_reduce(const int* __restrict__ y,
                                                const float* __restrict__ outb) {
    int warp = threadIdx.x >> 5, lane = threadIdx.x & 31;
    int row = blockIdx.x * 8 + warp;
    int t = row >> 8, b = row & 255;
    int n = y[(t + 1) * BATCH + b];

    const __nv_bfloat16* Ar = g_A  + (size_t)row * KP;
    const __nv_bfloat16* Wr = g_Wb + (size_t)n   * KP;
    float dot = 0.f;
    for (int k = lane; k < KP; k += 32)
        dot += __bfloat162float(Ar[k]) * __bfloat162float(Wr[k]);
    #pragma unroll
    for (int o = 16; o; o >>= 1) dot += __shfl_xor_sync(0xffffffffu, dot, o);
    dot += outb[n];

    float m = -3.4e38f, s = 0.f;
    for (int i = lane; i < NTILE; i += 32) {
        float tm = g_pM[(size_t)row * NTILE + i];
        float ts = g_pS[(size_t)row * NTILE + i];
        float nm = fmaxf(m, tm);
        s = s * __expf(m - nm) + ts * __expf(tm - nm);
        m = nm;
    }
    #pragma unroll
    for (int o = 16; o; o >>= 1) {
        float om = __shfl_xor_sync(0xffffffffu, m, o);
        float os = __shfl_xor_sync(0xffffffffu, s, o);
        float nm = fmaxf(m, om);
        s = s * __expf(m - nm) + os * __expf(om - nm);
        m = nm;
    }
    float ce = (m + __logf(s)) - dot;

    __shared__ float sm[8];
    if (lane == 0) sm[warp] = ce;
    __syncthreads();
    if (threadIdx.x == 0) {
        float tt = 0.f;
        #pragma unroll
        for (int i = 0; i < 8; i++) tt += sm[i];
        g_bsum[blockIdx.x] = tt;
    }
}

// ------------------------- final deterministic sum --------------------------
__global__ void k_final(float* out) {
    __shared__ double sm[256];
    int tid = threadIdx.x;
    double s = 0.0;
    for (int i = tid; i < 4064; i += 256) s += (double)g_bsum[i];
    sm[tid] = s;
    __syncthreads();
    for (int o = 128; o; o >>= 1) {
        if (tid < o) sm[tid] += sm[tid + o];
        __syncthreads();
    }
    if (tid == 0) out[0] = (float)(sm[0] * (1.0 / 256.0));
}

// ------------------------- launch -------------------------------------------
extern "C" void kernel_launch(void* const* d_in, const int* in_sizes, int n_in,
                              void* d_out, int out_size) {
    const int*   x       = (const int*)  d_in[0];
    const int*   y       = (const int*)  d_in[1];
    const float* enc_emb = (const float*)d_in[2];
    const float* encW    = (const float*)d_in[3];
    const float* encb    = (const float*)d_in[4];
    const float* dec_emb = (const float*)d_in[5];
    const float* decW    = (const float*)d_in[6];
    const float* decb    = (const float*)d_in[7];
    const float* outW    = (const float*)d_in[8];
    const float* outb    = (const float*)d_in[9];
    float* out = (float*)d_out;

    cudaFuncSetAttribute(k_gemm, cudaFuncAttributeMaxDynamicSharedMemorySize,
                         SMEM_GEMM);

    k_init<<<(MROWS * 4 + 255) / 256, 256>>>();
    k_convW<<<V, 320>>>(outW);

    // encoder: 128 steps, h0 = 0 in buffer 0
    for (int i = 0; i < NX; i++)
        k_step<<<dim3(75, 2), 256>>>(i & 1, (i + 1) & 1,
                                     x + i * BATCH, enc_emb, encW, encb, -1);
    // decoder: 127 steps (after encoder, h lives in buffer 0)
    for (int t = 0; t < NY - 1; t++)
        k_step<<<dim3(75, 2), 256>>>(t & 1, (t + 1) & 1,
                                     y + t * BATCH, dec_emb, decW, decb, t);

    k_gemm<<<dim3(NTILE, MTILE), 256, SMEM_GEMM>>>(outb);
    k_reduce<<<4064, 256>>>(y, outb);
    k_final<<<1, 256>>>(out);
}

// round 5
// speedup vs baseline: 1.4518x; 1.4518x over previous
#include <cuda_runtime.h>
#include <cuda_bf16.h>
#include <cstdint>

// ---------------------------------------------------------------------------
// RNNEncDec: persistent-kernel recurrence (255 fused steps, grid barrier)
// + bf16 tensor-core logits GEMM with fused streaming logsumexp.
// ---------------------------------------------------------------------------

#define H     300
#define BATCH 256
#define NX    128
#define NY    128
#define V     32000
#define MROWS (127 * 256)      // 32512
#define KP    304              // padded K
#define NTILE 250              // 32000 / 128
#define MTILE 254              // 32512 / 128
#define KS    312              // gemm smem row stride (halves)
#define SMEM_GEMM (2 * 128 * KS * 2)   // 159744 bytes

// recurrence persistent kernel geometry
#define GRID_R 100             // 25 j-tiles x 4 b-tiles (all co-resident)
#define JT     12              // j rows per block
#define BT     64              // b cols per block
#define CH     100             // k-chunk size (3 chunks of 100)
// dyn smem layout (bytes): W slices [2][12][300] f32, bias [2][12], 2 h bufs
#define SM_W    0
#define SM_B    (2 * JT * H * 4)           // 28800
#define SM_BUF0 29696                       // 16B aligned, after bias+pad
#define SM_BUF1 (SM_BUF0 + CH * BT * 4)    // +25600
#define SMEM_R  (SM_BUF1 + CH * BT * 4)    // 80896 total

// ------------------------- device scratch -----------------------------------
__device__ float g_h[2][H * BATCH];
__device__ __align__(16) __nv_bfloat16 g_A[(size_t)MROWS * KP];
__device__ __align__(16) __nv_bfloat16 g_Wb[(size_t)V * KP];
__device__ float g_pM[(size_t)MROWS * NTILE];
__device__ float g_pS[(size_t)MROWS * NTILE];
__device__ float g_bsum[4064];
__device__ unsigned g_barCnt;
__device__ unsigned g_barGen;

// ------------------------- init (each replay) -------------------------------
__global__ void k_init() {
    int i = blockIdx.x * blockDim.x + threadIdx.x;
    if (i == 0) { g_barCnt = 0; g_barGen = 0; }
    if (i < H * BATCH) g_h[0][i] = 0.f;
    if (i < MROWS * 4) {
        int row = i >> 2;
        g_A[(size_t)row * KP + 300 + (i & 3)] = __float2bfloat16(0.f);
    }
}

// ------------------------- outW fp32 -> bf16 (padded) -----------------------
__global__ void k_convW(const float* __restrict__ outW) {
    int n = blockIdx.x;
    int i = threadIdx.x;                 // 0..95 (75 data + 1 pad used)
    if (i < 75) {
        float4 v = *reinterpret_cast<const float4*>(outW + (size_t)n * H + i * 4);
        __nv_bfloat162 p0 = __floats2bfloat162_rn(v.x, v.y);
        __nv_bfloat162 p1 = __floats2bfloat162_rn(v.z, v.w);
        uint2 pk = make_uint2(*(uint32_t*)&p0, *(uint32_t*)&p1);
        *reinterpret_cast<uint2*>(g_Wb + (size_t)n * KP + i * 4) = pk;
    } else if (i == 75) {
        __nv_bfloat162 z = __floats2bfloat162_rn(0.f, 0.f);
        uint2 pk = make_uint2(*(uint32_t*)&z, *(uint32_t*)&z);
        *reinterpret_cast<uint2*>(g_Wb + (size_t)n * KP + 300) = pk;
    }
}

// ------------------------- cp.async helpers ---------------------------------
__device__ __forceinline__ void cpa16(void* dst, const void* src) {
    uint32_t d = (uint32_t)__cvta_generic_to_shared(dst);
    asm volatile("cp.async.cg.shared.global [%0], [%1], 16;\n" :: "r"(d), "l"(src));
}
#define CPA_COMMIT() asm volatile("cp.async.commit_group;\n" ::: "memory")
#define CPA_WAIT(n)  asm volatile("cp.async.wait_group %0;\n" :: "n"(n) : "memory")

// ------------------------- grid barrier -------------------------------------
__device__ __forceinline__ void gridbar(unsigned gen) {
    __threadfence();
    __syncthreads();
    if (threadIdx.x == 0) {
        unsigned t = atomicAdd(&g_barCnt, 1u);
        if (t == GRID_R - 1) {
            g_barCnt = 0;
            __threadfence();
            atomicExch(&g_barGen, gen);
        } else {
            unsigned v;
            do {
                asm volatile("ld.global.cg.u32 %0, [%1];" : "=r"(v) : "l"(&g_barGen));
                if (v >= gen) break;
                __nanosleep(40);
            } while (true);
        }
        __threadfence();
    }
    __syncthreads();
}

// ------------------------- persistent recurrence ----------------------------
__global__ void __launch_bounds__(256, 1) k_recur(
    const int*   __restrict__ x,
    const int*   __restrict__ y,
    const float* __restrict__ enc_emb,
    const float* __restrict__ encW,
    const float* __restrict__ encb,
    const float* __restrict__ dec_emb,
    const float* __restrict__ decW,
    const float* __restrict__ decb)
{
    extern __shared__ __align__(16) unsigned char smem[];
    float* sW  = reinterpret_cast<float*>(smem + SM_W);    // [2][12][300]
    float* sb  = reinterpret_cast<float*>(smem + SM_B);    // [2][12]
    float* buf0 = reinterpret_cast<float*>(smem + SM_BUF0);
    float* buf1 = reinterpret_cast<float*>(smem + SM_BUF1);

    int tid = threadIdx.x;
    int bx  = blockIdx.x;
    int j0  = (bx >> 2) * JT;          // 0..288 step 12
    int b0  = (bx & 3) * BT;           // 0,64,128,192
    int bl  = tid & 63;                // local b
    int jg  = tid >> 6;                // 0..3, each handles 3 j
    int jA  = j0 + jg * 3;             // absolute first j

    // load W slices + biases once
    for (int i = tid; i < 2 * JT * H; i += 256) {
        int bank = i / (JT * H);
        int r    = i - bank * (JT * H);
        int j    = r / H, k = r - j * H;
        const float* src = bank ? decW : encW;
        sW[i] = src[(size_t)(j0 + j) * H + k];
    }
    if (tid < JT)           sb[tid]          = encb[j0 + tid];
    else if (tid < 2 * JT)  sb[tid]          = decb[j0 + tid - JT];
    __syncthreads();

    for (int s = 0; s < NX + NY - 1 - 0; ++s) {          // 255 steps
        if (s >= 255) break;
        const float* hin  = g_h[s & 1];
        float*       hout = g_h[(s & 1) ^ 1];
        int dec = (s >= NX);
        int t   = s - NX;                                 // decoder step
        const int*   idxp = dec ? (y + t * BATCH) : (x + s * BATCH);
        const float* embp = dec ? dec_emb : enc_emb;
        const float* Wb   = sW + dec * (JT * H);
        const float* bb   = sb + dec * JT;

        // early embedding gather (hide DRAM latency behind compute)
        int e = idxp[b0 + bl];
        const float* erow = embp + (size_t)e * H + jA;
        float e0 = __ldg(erow), e1 = __ldg(erow + 1), e2 = __ldg(erow + 2);

        // stage chunk 0 and 1
        #pragma unroll 4
        for (int i = tid; i < CH * 16; i += 256) {
            int k = i >> 4, bq = i & 15;
            cpa16(buf0 + k * BT + bq * 4, hin + k * BATCH + b0 + bq * 4);
        }
        CPA_COMMIT();
        #pragma unroll 4
        for (int i = tid; i < CH * 16; i += 256) {
            int k = i >> 4, bq = i & 15;
            cpa16(buf1 + k * BT + bq * 4, hin + (CH + k) * BATCH + b0 + bq * 4);
        }
        CPA_COMMIT();

        float a0 = 0.f, a1 = 0.f, a2 = 0.f;

        // ---- chunk 0
        CPA_WAIT(1); __syncthreads();
        #pragma unroll 5
        for (int kk = 0; kk < CH; kk += 4) {
            float h0 = buf0[(kk + 0) * BT + bl];
            float h1 = buf0[(kk + 1) * BT + bl];
            float h2 = buf0[(kk + 2) * BT + bl];
            float h3 = buf0[(kk + 3) * BT + bl];
            float4 w;
            w = *reinterpret_cast<const float4*>(Wb + (jg * 3 + 0) * H + kk);
            a0 = fmaf(h3, w.w, fmaf(h2, w.z, fmaf(h1, w.y, fmaf(h0, w.x, a0))));
            w = *reinterpret_cast<const float4*>(Wb + (jg * 3 + 1) * H + kk);
            a1 = fmaf(h3, w.w, fmaf(h2, w.z, fmaf(h1, w.y, fmaf(h0, w.x, a1))));
            w = *reinterpret_cast<const float4*>(Wb + (jg * 3 + 2) * H + kk);
            a2 = fmaf(h3, w.w, fmaf(h2, w.z, fmaf(h1, w.y, fmaf(h0, w.x, a2))));
        }
        __syncthreads();                 // everyone done with buf0

        // stage chunk 2 into buf0
        #pragma unroll 4
        for (int i = tid; i < CH * 16; i += 256) {
            int k = i >> 4, bq = i & 15;
            cpa16(buf0 + k * BT + bq * 4, hin + (2 * CH + k) * BATCH + b0 + bq * 4);
        }
        CPA_COMMIT();

        // ---- chunk 1
        CPA_WAIT(1); __syncthreads();
        #pragma unroll 5
        for (int kk = 0; kk < CH; kk += 4) {
            float h0 = buf1[(kk + 0) * BT + bl];
            float h1 = buf1[(kk + 1) * BT + bl];
            float h2 = buf1[(kk + 2) * BT + bl];
            float h3 = buf1[(kk + 3) * BT + bl];
            float4 w;
            w = *reinterpret_cast<const float4*>(Wb + (jg * 3 + 0) * H + CH + kk);
            a0 = fmaf(h3, w.w, fmaf(h2, w.z, fmaf(h1, w.y, fmaf(h0, w.x, a0))));
            w = *reinterpret_cast<const float4*>(Wb + (jg * 3 + 1) * H + CH + kk);
            a1 = fmaf(h3, w.w, fmaf(h2, w.z, fmaf(h1, w.y, fmaf(h0, w.x, a1))));
            w = *reinterpret_cast<const float4*>(Wb + (jg * 3 + 2) * H + CH + kk);
            a2 = fmaf(h3, w.w, fmaf(h2, w.z, fmaf(h1, w.y, fmaf(h0, w.x, a2))));
        }

        // ---- chunk 2
        CPA_WAIT(0); __syncthreads();
        #pragma unroll 5
        for (int kk = 0; kk < CH; kk += 4) {
            float h0 = buf0[(kk + 0) * BT + bl];
            float h1 = buf0[(kk + 1) * BT + bl];
            float h2 = buf0[(kk + 2) * BT + bl];
            float h3 = buf0[(kk + 3) * BT + bl];
            float4 w;
            w = *reinterpret_cast<const float4*>(Wb + (jg * 3 + 0) * H + 2 * CH + kk);
            a0 = fmaf(h3, w.w, fmaf(h2, w.z, fmaf(h1, w.y, fmaf(h0, w.x, a0))));
            w = *reinterpret_cast<const float4*>(Wb + (jg * 3 + 1) * H + 2 * CH + kk);
            a1 = fmaf(h3, w.w, fmaf(h2, w.z, fmaf(h1, w.y, fmaf(h0, w.x, a1))));
            w = *reinterpret_cast<const float4*>(Wb + (jg * 3 + 2) * H + 2 * CH + kk);
            a2 = fmaf(h3, w.w, fmaf(h2, w.z, fmaf(h1, w.y, fmaf(h0, w.x, a2))));
        }

        // epilogue: + emb + bias, relu, store
        float v0 = fmaxf(a0 + e0 + bb[jg * 3 + 0], 0.f);
        float v1 = fmaxf(a1 + e1 + bb[jg * 3 + 1], 0.f);
        float v2 = fmaxf(a2 + e2 + bb[jg * 3 + 2], 0.f);
        int b = b0 + bl;
        hout[(jA + 0) * BATCH + b] = v0;
        hout[(jA + 1) * BATCH + b] = v1;
        hout[(jA + 2) * BATCH + b] = v2;
        if (dec) {
            __nv_bfloat16* ap = g_A + ((size_t)t * BATCH + b) * KP + jA;
            ap[0] = __float2bfloat16(v0);
            ap[1] = __float2bfloat16(v1);
            ap[2] = __float2bfloat16(v2);
        }

        gridbar((unsigned)(s + 1));
    }
}

// ------------------------- bf16 mma helper ----------------------------------
__device__ __forceinline__ void mma16816(float* c, const uint32_t* a,
                                         uint32_t b0, uint32_t b1) {
    asm volatile(
        "mma.sync.aligned.m16n8k16.row.col.f32.bf16.bf16.f32 "
        "{%0,%1,%2,%3}, {%4,%5,%6,%7}, {%8,%9}, {%0,%1,%2,%3};\n"
        : "+f"(c[0]), "+f"(c[1]), "+f"(c[2]), "+f"(c[3])
        : "r"(a[0]), "r"(a[1]), "r"(a[2]), "r"(a[3]), "r"(b0), "r"(b1));
}

// ------------------------- big GEMM + fused partial logsumexp ---------------
__global__ void __launch_bounds__(256) k_gemm(const float* __restrict__ outb) {
    extern __shared__ __align__(16) unsigned char smem_raw[];
    __nv_bfloat16* As = reinterpret_cast<__nv_bfloat16*>(smem_raw);
    __nv_bfloat16* Ws = As + 128 * KS;

    int tid = threadIdx.x;
    int m0 = blockIdx.y * 128;
    int n0 = blockIdx.x * 128;

    for (int i = tid; i < 128 * 38; i += 256) {
        int r = i / 38, c = i - r * 38;
        reinterpret_cast<uint4*>(As + r * KS)[c] =
            reinterpret_cast<const uint4*>(g_A + (size_t)(m0 + r) * KP)[c];
        reinterpret_cast<uint4*>(Ws + r * KS)[c] =
            reinterpret_cast<const uint4*>(g_Wb + (size_t)(n0 + r) * KP)[c];
    }
    __syncthreads();

    int warp = tid >> 5, lane = tid & 31;
    int wm = warp & 3, wn = warp >> 2;
    int g = lane >> 2, tig = lane & 3;

    float acc[2][8][4];
    #pragma unroll
    for (int a = 0; a < 2; a++)
        #pragma unroll
        for (int b = 0; b < 8; b++)
            #pragma unroll
            for (int q = 0; q < 4; q++) acc[a][b][q] = 0.f;

    const __nv_bfloat16* Abase = As + (wm * 32 + g) * KS + tig * 2;
    const __nv_bfloat16* Bbase = Ws + (wn * 64 + g) * KS + tig * 2;

    #pragma unroll 1
    for (int kc = 0; kc < 19; kc++) {
        int kb = kc * 16;
        uint32_t afr[2][4];
        #pragma unroll
        for (int mt = 0; mt < 2; mt++) {
            const __nv_bfloat16* p = Abase + mt * 16 * KS + kb;
            afr[mt][0] = *reinterpret_cast<const uint32_t*>(p);
            afr[mt][1] = *reinterpret_cast<const uint32_t*>(p + 8 * KS);
            afr[mt][2] = *reinterpret_cast<const uint32_t*>(p + 8);
            afr[mt][3] = *reinterpret_cast<const uint32_t*>(p + 8 * KS + 8);
        }
        #pragma unroll
        for (int nt = 0; nt < 8; nt++) {
            const __nv_bfloat16* p = Bbase + nt * 8 * KS + kb;
            uint32_t b0 = *reinterpret_cast<const uint32_t*>(p);
            uint32_t b1 = *reinterpret_cast<const uint32_t*>(p + 8);
            mma16816(acc[0][nt], afr[0], b0, b1);
            mma16816(acc[1][nt], afr[1], b0, b1);
        }
    }
    __syncthreads();

    #pragma unroll
    for (int nt = 0; nt < 8; nt++) {
        float bv0 = outb[n0 + wn * 64 + nt * 8 + tig * 2];
        float bv1 = outb[n0 + wn * 64 + nt * 8 + tig * 2 + 1];
        #pragma unroll
        for (int mt = 0; mt < 2; mt++) {
            acc[mt][nt][0] += bv0; acc[mt][nt][1] += bv1;
            acc[mt][nt][2] += bv0; acc[mt][nt][3] += bv1;
        }
    }

    float rm[4], rs[4];
    #pragma unroll
    for (int r = 0; r < 4; r++) {
        int mt = r >> 1, hi = r & 1;
        float mx = -3.4e38f;
        #pragma unroll
        for (int nt = 0; nt < 8; nt++) {
            mx = fmaxf(mx, acc[mt][nt][hi * 2]);
            mx = fmaxf(mx, acc[mt][nt][hi * 2 + 1]);
        }
        mx = fmaxf(mx, __shfl_xor_sync(0xffffffffu, mx, 1));
        mx = fmaxf(mx, __shfl_xor_sync(0xffffffffu, mx, 2));
        float s = 0.f;
        #pragma unroll
        for (int nt = 0; nt < 8; nt++) {
            s += __expf(acc[mt][nt][hi * 2]     - mx);
            s += __expf(acc[mt][nt][hi * 2 + 1] - mx);
        }
        s += __shfl_xor_sync(0xffffffffu, s, 1);
        s += __shfl_xor_sync(0xffffffffu, s, 2);
        rm[r] = mx; rs[r] = s;
    }

    float* red = reinterpret_cast<float*>(smem_raw);
    if (wn == 0 && tig == 0) {
        #pragma unroll
        for (int r = 0; r < 4; r++) {
            int rowL = wm * 32 + (r >> 1) * 16 + (r & 1) * 8 + g;
            red[rowL * 2]     = rm[r];
            red[rowL * 2 + 1] = rs[r];
        }
    }
    __syncthreads();
    if (wn == 1 && tig == 0) {
        #pragma unroll
        for (int r = 0; r < 4; r++) {
            int rowL = wm * 32 + (r >> 1) * 16 + (r & 1) * 8 + g;
            float om = red[rowL * 2], os = red[rowL * 2 + 1];
            float nm = fmaxf(rm[r], om);
            float s  = rs[r] * __expf(rm[r] - nm) + os * __expf(om - nm);
            size_t grow = (size_t)(m0 + rowL);
            g_pM[grow * NTILE + blockIdx.x] = nm;
            g_pS[grow * NTILE + blockIdx.x] = s;
        }
    }
}

// ------------------------- per-row lse + target logit -> CE -----------------
__global__ void __launch_bounds__(256) k_reduce(const int* __restrict__ y,
                                                const float* __restrict__ outb) {
    int warp = threadIdx.x >> 5, lane = threadIdx.x & 31;
    int row = blockIdx.x * 8 + warp;
    int t = row >> 8, b = row & 255;
    int n = y[(t + 1) * BATCH + b];

    const __nv_bfloat16* Ar = g_A  + (size_t)row * KP;
    const __nv_bfloat16* Wr = g_Wb + (size_t)n   * KP;
    float dot = 0.f;
    for (int k = lane; k < KP; k += 32)
        dot += __bfloat162float(Ar[k]) * __bfloat162float(Wr[k]);
    #pragma unroll
    for (int o = 16; o; o >>= 1) dot += __shfl_xor_sync(0xffffffffu, dot, o);
    dot += outb[n];

    float m = -3.4e38f, s = 0.f;
    for (int i = lane; i < NTILE; i += 32) {
        float tm = g_pM[(size_t)row * NTILE + i];
        float ts = g_pS[(size_t)row * NTILE + i];
        float nm = fmaxf(m, tm);
        s = s * __expf(m - nm) + ts * __expf(tm - nm);
        m = nm;
    }
    #pragma unroll
    for (int o = 16; o; o >>= 1) {
        float om = __shfl_xor_sync(0xffffffffu, m, o);
        float os = __shfl_xor_sync(0xffffffffu, s, o);
        float nm = fmaxf(m, om);
        s = s * __expf(m - nm) + os * __expf(om - nm);
        m = nm;
    }
    float ce = (m + __logf(s)) - dot;

    __shared__ float sm[8];
    if (lane == 0) sm[warp] = ce;
    __syncthreads();
    if (threadIdx.x == 0) {
        float tt = 0.f;
        #pragma unroll
        for (int i = 0; i < 8; i++) tt += sm[i];
        g_bsum[blockIdx.x] = tt;
    }
}

// ------------------------- final deterministic sum --------------------------
__global__ void k_final(float* out) {
    __shared__ double sm[256];
    int tid = threadIdx.x;
    double s = 0.0;
    for (int i = tid; i < 4064; i += 256) s += (double)g_bsum[i];
    sm[tid] = s;
    __syncthreads();
    for (int o = 128; o; o >>= 1) {
        if (tid < o) sm[tid] += sm[tid + o];
        __syncthreads();
    }
    if (tid == 0) out[0] = (float)(sm[0] * (1.0 / 256.0));
}

// ------------------------- launch -------------------------------------------
extern "C" void kernel_launch(void* const* d_in, const int* in_sizes, int n_in,
                              void* d_out, int out_size) {
    const int*   x       = (const int*)  d_in[0];
    const int*   y       = (const int*)  d_in[1];
    const float* enc_emb = (const float*)d_in[2];
    const float* encW    = (const float*)d_in[3];
    const float* encb    = (const float*)d_in[4];
    const float* dec_emb = (const float*)d_in[5];
    const float* decW    = (const float*)d_in[6];
    const float* decb    = (const float*)d_in[7];
    const float* outW    = (const float*)d_in[8];
    const float* outb    = (const float*)d_in[9];
    float* out = (float*)d_out;

    cudaFuncSetAttribute(k_gemm, cudaFuncAttributeMaxDynamicSharedMemorySize,
                         SMEM_GEMM);
    cudaFuncSetAttribute(k_recur, cudaFuncAttributeMaxDynamicSharedMemorySize,
                         SMEM_R);

    k_init<<<(MROWS * 4 + 255) / 256, 256>>>();
    k_convW<<<V, 96>>>(outW);

    k_recur<<<GRID_R, 256, SMEM_R>>>(x, y, enc_emb, encW, encb,
                                     dec_emb, decW, decb);

    k_gemm<<<dim3(NTILE, MTILE), 256, SMEM_GEMM>>>(outb);
    k_reduce<<<4064, 256>>>(y, outb);
    k_final<<<1, 256>>>(out);
}